// round 8
// baseline (speedup 1.0000x reference)
#include <cuda_runtime.h>
#include <cstdint>

#define DIMX 32
#define NB   6
#define BB   16
#define NN   256
#define XPD  16
#define TPD  8

#define TOTAL   (BB * NN * NN)       // 1,048,576 pairs
#define TPB     256
#define PPT     3                    // pairs per thread
#define PPB     (TPB * PPT)          // 768 pairs per block
#define GRID    ((TOTAL + PPB - 1) / PPB)   // 1366

typedef unsigned long long u64;

__device__ __align__(16) float g_cf[BB * NB * DIMX];
__device__ __align__(16) float g_cg[BB * NB * DIMX];

// ---------------- packed f32x2 helpers ----------------
__device__ __forceinline__ u64 ffma2(u64 a, u64 b, u64 c) {
    u64 d;
    asm("fma.rn.f32x2 %0, %1, %2, %3;" : "=l"(d) : "l"(a), "l"(b), "l"(c));
    return d;
}
__device__ __forceinline__ u64 pack2(float v) {
    u64 r;
    asm("mov.b64 %0, {%1, %1};" : "=l"(r) : "f"(v));
    return r;
}
__device__ __forceinline__ float2 unpack2(u64 v) {
    float lo, hi;
    asm("mov.b64 {%0, %1}, %2;" : "=f"(lo), "=f"(hi) : "l"(v));
    return make_float2(lo, hi);
}

// ---------------- precompute: embeddings + folded constants ----------------
__global__ void precompute_kernel(
    const float* __restrict__ x_params, const float* __restrict__ t_params,
    const float* __restrict__ xW1, const float* __restrict__ xb1,
    const float* __restrict__ xW2, const float* __restrict__ xb2,
    const float* __restrict__ tW1, const float* __restrict__ tb1,
    const float* __restrict__ tW2, const float* __restrict__ tb2,
    const float* __restrict__ f_bh, const float* __restrict__ f_Wz, const float* __restrict__ f_bz,
    const float* __restrict__ g_bh, const float* __restrict__ g_Wz, const float* __restrict__ g_bz,
    const float* __restrict__ h0,   const float* __restrict__ gh0,
    const float* __restrict__ f_Wh, const float* __restrict__ g_Wh)
{
    int b = blockIdx.x;
    int d = threadIdx.x;  // 0..31
    __shared__ float hid[DIMX], ex_s[DIMX], et_s[DIMX];

    float a = xb1[d];
    #pragma unroll
    for (int m = 0; m < XPD; m++) a += x_params[b * XPD + m] * xW1[m * DIMX + d];
    hid[d] = sinf(a);
    __syncthreads();
    float e = xb2[d];
    #pragma unroll
    for (int m = 0; m < DIMX; m++) e += hid[m] * xW2[m * DIMX + d];
    ex_s[d] = e;
    __syncthreads();

    a = tb1[d];
    #pragma unroll
    for (int m = 0; m < TPD; m++) a += t_params[b * TPD + m] * tW1[m * DIMX + d];
    hid[d] = sinf(a);
    __syncthreads();
    e = tb2[d];
    #pragma unroll
    for (int m = 0; m < DIMX; m++) e += hid[m] * tW2[m * DIMX + d];
    et_s[d] = e;
    __syncthreads();

    for (int k = 0; k < NB; k++) {
        float cf = f_bh[k * DIMX + d] + f_bz[k * DIMX + d];
        const float* Wz = f_Wz + k * 34 * DIMX;
        #pragma unroll
        for (int m = 0; m < DIMX; m++) cf += et_s[m] * Wz[(2 + m) * DIMX + d];
        if (k == 0) {
            #pragma unroll
            for (int m = 0; m < DIMX; m++) cf += h0[m] * f_Wh[m * DIMX + d];
        }
        g_cf[(b * NB + k) * DIMX + d] = cf;

        float cg = g_bh[k * DIMX + d] + g_bz[k * DIMX + d];
        const float* gWz = g_Wz + k * 64 * DIMX;
        #pragma unroll
        for (int m = 0; m < DIMX; m++) cg += ex_s[m] * gWz[(32 + m) * DIMX + d];
        if (k == 0) {
            #pragma unroll
            for (int m = 0; m < DIMX; m++) cg += gh0[m] * g_Wh[m * DIMX + d];
        }
        g_cg[(b * NB + k) * DIMX + d] = cg;
    }
}

// ---------------- main kernel ----------------
#define OFF_FWH 0        // f_Wh[1..5]   5*1024
#define OFF_GWH 5120     // g_Wh[1..5]   5*1024
#define OFF_GWZ 10240    // g_Wz[0..5] rows 0..31   6*1024
#define OFF_WZX 16384    // 6*32
#define OFF_WZT 16576
#define OFF_DW  16768    // 32
#define OFF_DB  16800
#define OFF_H   16832    // final-h state: 3 * 32 * 256 floats
#define SMEM_FLOATS 41408
#define SMEM_BYTES  (SMEM_FLOATS * 4)   // 165632 B

extern __shared__ float smem[];

__global__ void __launch_bounds__(TPB, 1) pde_kernel(
    const float* __restrict__ coords,
    const float* __restrict__ f_Wh,
    const float* __restrict__ g_Wh,
    const float* __restrict__ g_Wz,
    const float* __restrict__ f_Wz,
    const float* __restrict__ dW,
    const float* __restrict__ dB,
    float* __restrict__ out)
{
    const int tid = threadIdx.x;

    // ---- cooperative staging ----
    for (int q = tid; q < 1280; q += TPB) {
        int k = q >> 8, r = q & 255;
        ((float4*)(smem + OFF_FWH))[q] = ((const float4*)(f_Wh + (k + 1) * 1024))[r];
    }
    for (int q = tid; q < 1280; q += TPB) {
        int k = q >> 8, r = q & 255;
        ((float4*)(smem + OFF_GWH))[q] = ((const float4*)(g_Wh + (k + 1) * 1024))[r];
    }
    for (int q = tid; q < 1536; q += TPB) {
        int k = q >> 8, r = q & 255;
        ((float4*)(smem + OFF_GWZ))[q] = ((const float4*)(g_Wz + k * 2048))[r];
    }
    if (tid < 192) {
        int k = tid >> 5, d = tid & 31;
        smem[OFF_WZX + tid] = f_Wz[k * 34 * DIMX + d];
        smem[OFF_WZT + tid] = f_Wz[k * 34 * DIMX + DIMX + d];
    }
    if (tid < 32) smem[OFF_DW + tid] = dW[tid];
    if (tid == 0) smem[OFF_DB] = dB[0];
    __syncthreads();

    // ---- 3 pairs per thread ----
    const int pbase = blockIdx.x * PPB + tid;
    int   pp[PPT];
    bool  valid[PPT];
    const float* cfb[PPT];
    const float* cgb[PPT];
    float xv[PPT], tv[PPT];
    u64   xx[PPT], ttv[PPT];

    #pragma unroll
    for (int m = 0; m < PPT; m++) {
        int p = pbase + m * TPB;
        valid[m] = (p < TOTAL);
        if (p >= TOTAL) p = TOTAL - 1;
        pp[m] = p;
        int b = p >> 16;
        int i = (p >> 8) & 255;
        int j = p & 255;
        xv[m] = coords[(b * NN + j) * 2 + 0];
        tv[m] = coords[(b * NN + i) * 2 + 1];
        xx[m]  = pack2(xv[m]);
        ttv[m] = pack2(tv[m]);
        cfb[m] = g_cf + b * (NB * DIMX);
        cgb[m] = g_cg + b * (NB * DIMX);
    }

    float h0r[DIMX], h1r[DIMX], h2r[DIMX];

    // ---- f layer 0 (h0@Wh0 folded into cf0) ----
    {
        const float4* wx4 = (const float4*)(smem + OFF_WZX);
        const float4* wt4 = (const float4*)(smem + OFF_WZT);
        const float4* c0 = (const float4*)(cfb[0]);
        const float4* c1 = (const float4*)(cfb[1]);
        const float4* c2 = (const float4*)(cfb[2]);
        #pragma unroll
        for (int q = 0; q < 8; q++) {
            float4 a = wx4[q], bq = wt4[q];
            float4 e0 = c0[q], e1 = c1[q], e2 = c2[q];
            h0r[4*q+0] = __sinf(fmaf(xv[0], a.x, fmaf(tv[0], bq.x, e0.x)));
            h0r[4*q+1] = __sinf(fmaf(xv[0], a.y, fmaf(tv[0], bq.y, e0.y)));
            h0r[4*q+2] = __sinf(fmaf(xv[0], a.z, fmaf(tv[0], bq.z, e0.z)));
            h0r[4*q+3] = __sinf(fmaf(xv[0], a.w, fmaf(tv[0], bq.w, e0.w)));
            h1r[4*q+0] = __sinf(fmaf(xv[1], a.x, fmaf(tv[1], bq.x, e1.x)));
            h1r[4*q+1] = __sinf(fmaf(xv[1], a.y, fmaf(tv[1], bq.y, e1.y)));
            h1r[4*q+2] = __sinf(fmaf(xv[1], a.z, fmaf(tv[1], bq.z, e1.z)));
            h1r[4*q+3] = __sinf(fmaf(xv[1], a.w, fmaf(tv[1], bq.w, e1.w)));
            h2r[4*q+0] = __sinf(fmaf(xv[2], a.x, fmaf(tv[2], bq.x, e2.x)));
            h2r[4*q+1] = __sinf(fmaf(xv[2], a.y, fmaf(tv[2], bq.y, e2.y)));
            h2r[4*q+2] = __sinf(fmaf(xv[2], a.z, fmaf(tv[2], bq.z, e2.z)));
            h2r[4*q+3] = __sinf(fmaf(xv[2], a.w, fmaf(tv[2], bq.w, e2.w)));
        }
    }

    // ---- f layers 1..5: h in regs, each weight LDS feeds 6 FFMA2 ----
    #pragma unroll 1
    for (int k = 1; k < 6; k++) {
        u64 a0[16], a1[16], a2[16];
        {
            const ulonglong2* wx = (const ulonglong2*)(smem + OFF_WZX + k * 32);
            const ulonglong2* wt = (const ulonglong2*)(smem + OFF_WZT + k * 32);
            const ulonglong2* c0 = (const ulonglong2*)(cfb[0] + k * 32);
            const ulonglong2* c1 = (const ulonglong2*)(cfb[1] + k * 32);
            const ulonglong2* c2 = (const ulonglong2*)(cfb[2] + k * 32);
            #pragma unroll
            for (int q = 0; q < 8; q++) {
                ulonglong2 ax = wx[q], bt = wt[q];
                ulonglong2 e0 = c0[q], e1 = c1[q], e2 = c2[q];
                a0[2*q]   = ffma2(xx[0], ax.x, ffma2(ttv[0], bt.x, e0.x));
                a0[2*q+1] = ffma2(xx[0], ax.y, ffma2(ttv[0], bt.y, e0.y));
                a1[2*q]   = ffma2(xx[1], ax.x, ffma2(ttv[1], bt.x, e1.x));
                a1[2*q+1] = ffma2(xx[1], ax.y, ffma2(ttv[1], bt.y, e1.y));
                a2[2*q]   = ffma2(xx[2], ax.x, ffma2(ttv[2], bt.x, e2.x));
                a2[2*q+1] = ffma2(xx[2], ax.y, ffma2(ttv[2], bt.y, e2.y));
            }
        }
        const ulonglong2* W = (const ulonglong2*)(smem + OFF_FWH + (k - 1) * 1024);
        #pragma unroll
        for (int kk = 0; kk < 32; kk++) {
            u64 v0 = pack2(h0r[kk]);
            u64 v1 = pack2(h1r[kk]);
            u64 v2 = pack2(h2r[kk]);
            #pragma unroll
            for (int q = 0; q < 8; q++) {
                ulonglong2 w = W[kk * 8 + q];
                a0[2*q]   = ffma2(v0, w.x, a0[2*q]);
                a0[2*q+1] = ffma2(v0, w.y, a0[2*q+1]);
                a1[2*q]   = ffma2(v1, w.x, a1[2*q]);
                a1[2*q+1] = ffma2(v1, w.y, a1[2*q+1]);
                a2[2*q]   = ffma2(v2, w.x, a2[2*q]);
                a2[2*q+1] = ffma2(v2, w.y, a2[2*q+1]);
            }
        }
        #pragma unroll
        for (int q = 0; q < 16; q++) {
            float2 r0 = unpack2(a0[q]);
            float2 r1 = unpack2(a1[q]);
            float2 r2 = unpack2(a2[q]);
            h0r[2*q]   = __sinf(r0.x);  h0r[2*q+1] = __sinf(r0.y);
            h1r[2*q]   = __sinf(r1.x);  h1r[2*q+1] = __sinf(r1.y);
            h2r[2*q]   = __sinf(r2.x);  h2r[2*q+1] = __sinf(r2.y);
        }
    }

    // ---- persist final h to smem (3 column arrays) ----
    float* h0_s = smem + OFF_H + tid;
    float* h1_s = smem + OFF_H + 8192 + tid;
    float* h2_s = smem + OFF_H + 16384 + tid;
    #pragma unroll
    for (int kk = 0; kk < 32; kk++) {
        h0_s[kk * TPB] = h0r[kk];
        h1_s[kk * TPB] = h1r[kk];
        h2_s[kk * TPB] = h2r[kk];
    }

    // ---- g layer 0: gh = sin(h @ gWz0 + cg0), h still in regs ----
    float g0r[DIMX], g1r[DIMX], g2r[DIMX];
    {
        u64 a0[16], a1[16], a2[16];
        {
            const ulonglong2* c0 = (const ulonglong2*)(cgb[0]);
            const ulonglong2* c1 = (const ulonglong2*)(cgb[1]);
            const ulonglong2* c2 = (const ulonglong2*)(cgb[2]);
            #pragma unroll
            for (int q = 0; q < 8; q++) {
                ulonglong2 e0 = c0[q], e1 = c1[q], e2 = c2[q];
                a0[2*q] = e0.x; a0[2*q+1] = e0.y;
                a1[2*q] = e1.x; a1[2*q+1] = e1.y;
                a2[2*q] = e2.x; a2[2*q+1] = e2.y;
            }
        }
        const ulonglong2* W = (const ulonglong2*)(smem + OFF_GWZ);
        #pragma unroll
        for (int kk = 0; kk < 32; kk++) {
            u64 v0 = pack2(h0r[kk]);
            u64 v1 = pack2(h1r[kk]);
            u64 v2 = pack2(h2r[kk]);
            #pragma unroll
            for (int q = 0; q < 8; q++) {
                ulonglong2 w = W[kk * 8 + q];
                a0[2*q]   = ffma2(v0, w.x, a0[2*q]);
                a0[2*q+1] = ffma2(v0, w.y, a0[2*q+1]);
                a1[2*q]   = ffma2(v1, w.x, a1[2*q]);
                a1[2*q+1] = ffma2(v1, w.y, a1[2*q+1]);
                a2[2*q]   = ffma2(v2, w.x, a2[2*q]);
                a2[2*q+1] = ffma2(v2, w.y, a2[2*q+1]);
            }
        }
        #pragma unroll
        for (int q = 0; q < 16; q++) {
            float2 r0 = unpack2(a0[q]);
            float2 r1 = unpack2(a1[q]);
            float2 r2 = unpack2(a2[q]);
            g0r[2*q]   = __sinf(r0.x);  g0r[2*q+1] = __sinf(r0.y);
            g1r[2*q]   = __sinf(r1.x);  g1r[2*q+1] = __sinf(r1.y);
            g2r[2*q]   = __sinf(r2.x);  g2r[2*q+1] = __sinf(r2.y);
        }
    }

    // ---- g layers 1..5: gh in regs, h from smem; decode folded into k==5 ----
    float u0 = smem[OFF_DB], u1 = u0, u2 = u0;
    #pragma unroll 1
    for (int k = 1; k < 6; k++) {
        u64 a0[16], a1[16], a2[16];
        {
            const ulonglong2* c0 = (const ulonglong2*)(cgb[0] + k * 32);
            const ulonglong2* c1 = (const ulonglong2*)(cgb[1] + k * 32);
            const ulonglong2* c2 = (const ulonglong2*)(cgb[2] + k * 32);
            #pragma unroll
            for (int q = 0; q < 8; q++) {
                ulonglong2 e0 = c0[q], e1 = c1[q], e2 = c2[q];
                a0[2*q] = e0.x; a0[2*q+1] = e0.y;
                a1[2*q] = e1.x; a1[2*q+1] = e1.y;
                a2[2*q] = e2.x; a2[2*q+1] = e2.y;
            }
        }
        const ulonglong2* Wh = (const ulonglong2*)(smem + OFF_GWH + (k - 1) * 1024);
        const ulonglong2* Wz = (const ulonglong2*)(smem + OFF_GWZ + k * 1024);
        #pragma unroll
        for (int kk = 0; kk < 32; kk++) {
            u64 gv0 = pack2(g0r[kk]);
            u64 gv1 = pack2(g1r[kk]);
            u64 gv2 = pack2(g2r[kk]);
            u64 hv0 = pack2(h0_s[kk * TPB]);
            u64 hv1 = pack2(h1_s[kk * TPB]);
            u64 hv2 = pack2(h2_s[kk * TPB]);
            #pragma unroll
            for (int q = 0; q < 8; q++) {
                ulonglong2 wh = Wh[kk * 8 + q];
                ulonglong2 wz = Wz[kk * 8 + q];
                a0[2*q]   = ffma2(gv0, wh.x, a0[2*q]);
                a0[2*q]   = ffma2(hv0, wz.x, a0[2*q]);
                a0[2*q+1] = ffma2(gv0, wh.y, a0[2*q+1]);
                a0[2*q+1] = ffma2(hv0, wz.y, a0[2*q+1]);
                a1[2*q]   = ffma2(gv1, wh.x, a1[2*q]);
                a1[2*q]   = ffma2(hv1, wz.x, a1[2*q]);
                a1[2*q+1] = ffma2(gv1, wh.y, a1[2*q+1]);
                a1[2*q+1] = ffma2(hv1, wz.y, a1[2*q+1]);
                a2[2*q]   = ffma2(gv2, wh.x, a2[2*q]);
                a2[2*q]   = ffma2(hv2, wz.x, a2[2*q]);
                a2[2*q+1] = ffma2(gv2, wh.y, a2[2*q+1]);
                a2[2*q+1] = ffma2(hv2, wz.y, a2[2*q+1]);
            }
        }
        if (k < 5) {
            #pragma unroll
            for (int q = 0; q < 16; q++) {
                float2 r0 = unpack2(a0[q]);
                float2 r1 = unpack2(a1[q]);
                float2 r2 = unpack2(a2[q]);
                g0r[2*q]   = __sinf(r0.x);  g0r[2*q+1] = __sinf(r0.y);
                g1r[2*q]   = __sinf(r1.x);  g1r[2*q+1] = __sinf(r1.y);
                g2r[2*q]   = __sinf(r2.x);  g2r[2*q+1] = __sinf(r2.y);
            }
        } else {
            const float* dw = smem + OFF_DW;
            #pragma unroll
            for (int q = 0; q < 16; q++) {
                float2 r0 = unpack2(a0[q]);
                float2 r1 = unpack2(a1[q]);
                float2 r2 = unpack2(a2[q]);
                float w0 = dw[2*q], w1 = dw[2*q+1];
                u0 = fmaf(__sinf(r0.x), w0, u0);
                u0 = fmaf(__sinf(r0.y), w1, u0);
                u1 = fmaf(__sinf(r1.x), w0, u1);
                u1 = fmaf(__sinf(r1.y), w1, u1);
                u2 = fmaf(__sinf(r2.x), w0, u2);
                u2 = fmaf(__sinf(r2.y), w1, u2);
            }
        }
    }

    if (valid[0]) out[pp[0]] = u0;
    if (valid[1]) out[pp[1]] = u1;
    if (valid[2]) out[pp[2]] = u2;
}

extern "C" void kernel_launch(void* const* d_in, const int* in_sizes, int n_in,
                              void* d_out, int out_size) {
    const float* coords   = (const float*)d_in[0];
    const float* x_params = (const float*)d_in[1];
    const float* t_params = (const float*)d_in[2];
    const float* xW1 = (const float*)d_in[3];
    const float* xb1 = (const float*)d_in[4];
    const float* xW2 = (const float*)d_in[5];
    const float* xb2 = (const float*)d_in[6];
    const float* tW1 = (const float*)d_in[7];
    const float* tb1 = (const float*)d_in[8];
    const float* tW2 = (const float*)d_in[9];
    const float* tb2 = (const float*)d_in[10];
    const float* h0  = (const float*)d_in[11];
    const float* gh0 = (const float*)d_in[12];
    const float* f_Wh = (const float*)d_in[13];
    const float* f_bh = (const float*)d_in[14];
    const float* f_Wz = (const float*)d_in[15];
    const float* f_bz = (const float*)d_in[16];
    const float* g_Wh = (const float*)d_in[17];
    const float* g_bh = (const float*)d_in[18];
    const float* g_Wz = (const float*)d_in[19];
    const float* g_bz = (const float*)d_in[20];
    const float* dW   = (const float*)d_in[21];
    const float* dB   = (const float*)d_in[22];

    precompute_kernel<<<BB, 32>>>(x_params, t_params, xW1, xb1, xW2, xb2,
                                  tW1, tb1, tW2, tb2,
                                  f_bh, f_Wz, f_bz, g_bh, g_Wz, g_bz,
                                  h0, gh0, f_Wh, g_Wh);

    cudaFuncSetAttribute(pde_kernel, cudaFuncAttributeMaxDynamicSharedMemorySize, SMEM_BYTES);

    pde_kernel<<<GRID, TPB, SMEM_BYTES>>>(coords, f_Wh, g_Wh, g_Wz, f_Wz,
                                          dW, dB, (float*)d_out);
}